// round 2
// baseline (speedup 1.0000x reference)
#include <cuda_runtime.h>
#include <math.h>

#define D_MODEL 1024
#define NHEAD   16
#define DK      64
#define BATCH   4
#define SEQ     2048
#define M_ROWS  (BATCH*SEQ)   // 8192

// Scratch (static device globals; no runtime allocation)
__device__ float g_Q[BATCH*NHEAD*SEQ*DK];   // [B,H,T,dk]
__device__ float g_K[BATCH*NHEAD*SEQ*DK];
__device__ float g_V[BATCH*NHEAD*SEQ*DK];
__device__ float g_ctx[M_ROWS*D_MODEL];     // [B*T, D]

// ---------------------------------------------------------------------------
// GEMM: Y[m,e] = sum_k (A[m,k]+addA) * W[e,k] + bias[e], with epilogue clip.
// WHICH: 0/1/2 -> A from param, write Q/K/V head layout [B,H,T,dk], clip +-10
//        3     -> A = g_ctx (device global, read in device code), write
//                 row-major [M,N] to `outp` with clip +-100
// Tiles: 64x64x16, 256 threads, 4x4 per-thread micro-tile.
// ---------------------------------------------------------------------------
template<int WHICH>
__global__ __launch_bounds__(256)
void nsattn_gemm_kernel(const float* __restrict__ Ain,
                        const float* __restrict__ W,
                        const float* __restrict__ bias,
                        float* __restrict__ outp,
                        int K, float addA)
{
    __shared__ float As[16][64];
    __shared__ float Bs[16][64];

    const float* A = (WHICH == 3) ? (const float*)g_ctx : Ain;

    const int bx = blockIdx.x;            // N tile (16 tiles)
    const int by = blockIdx.y;            // M tile (128 tiles)
    const int tid = threadIdx.x;          // 0..255
    const int tx = tid & 15;
    const int ty = tid >> 4;

    const int lrow  = tid >> 2;           // 0..63
    const int lcol4 = (tid & 3) * 4;      // 0,4,8,12

    const float* Aptr = A + (size_t)(by*64 + lrow)*K + lcol4;
    const float* Wptr = W + (size_t)(bx*64 + lrow)*K + lcol4;

    float c[4][4];
    #pragma unroll
    for (int i=0;i<4;i++)
        #pragma unroll
        for (int j=0;j<4;j++) c[i][j]=0.f;

    for (int k0 = 0; k0 < K; k0 += 16) {
        float4 av = *(const float4*)(Aptr + k0);
        float4 wv = *(const float4*)(Wptr + k0);
        __syncthreads();
        As[lcol4+0][lrow] = av.x + addA;
        As[lcol4+1][lrow] = av.y + addA;
        As[lcol4+2][lrow] = av.z + addA;
        As[lcol4+3][lrow] = av.w + addA;
        Bs[lcol4+0][lrow] = wv.x;
        Bs[lcol4+1][lrow] = wv.y;
        Bs[lcol4+2][lrow] = wv.z;
        Bs[lcol4+3][lrow] = wv.w;
        __syncthreads();
        #pragma unroll
        for (int kk = 0; kk < 16; kk++) {
            float4 a = *(const float4*)&As[kk][ty*4];
            float4 b = *(const float4*)&Bs[kk][tx*4];
            c[0][0] += a.x*b.x; c[0][1] += a.x*b.y; c[0][2] += a.x*b.z; c[0][3] += a.x*b.w;
            c[1][0] += a.y*b.x; c[1][1] += a.y*b.y; c[1][2] += a.y*b.z; c[1][3] += a.y*b.w;
            c[2][0] += a.z*b.x; c[2][1] += a.z*b.y; c[2][2] += a.z*b.z; c[2][3] += a.z*b.w;
            c[3][0] += a.w*b.x; c[3][1] += a.w*b.y; c[3][2] += a.w*b.z; c[3][3] += a.w*b.w;
        }
    }

    const int e0 = bx*64 + tx*4;
    const float b0 = bias[e0+0], b1 = bias[e0+1], b2 = bias[e0+2], b3 = bias[e0+3];

    #pragma unroll
    for (int rr = 0; rr < 4; rr++) {
        const int m = by*64 + ty*4 + rr;
        float4 v;
        if (WHICH < 3) {
            v.x = fminf(fmaxf(c[rr][0] + b0, -10.f), 10.f);
            v.y = fminf(fmaxf(c[rr][1] + b1, -10.f), 10.f);
            v.z = fminf(fmaxf(c[rr][2] + b2, -10.f), 10.f);
            v.w = fminf(fmaxf(c[rr][3] + b3, -10.f), 10.f);
            const int b_ = m >> 11;          // m / SEQ
            const int t  = m & (SEQ-1);
            const int h  = e0 >> 6;          // e0 / DK
            const int dd = e0 & (DK-1);
            float* dst = (WHICH==0) ? g_Q : (WHICH==1) ? g_K : g_V;
            *(float4*)&dst[(((size_t)(b_*NHEAD + h))*SEQ + t)*DK + dd] = v;
        } else {
            v.x = fminf(fmaxf(c[rr][0] + b0, -100.f), 100.f);
            v.y = fminf(fmaxf(c[rr][1] + b1, -100.f), 100.f);
            v.z = fminf(fmaxf(c[rr][2] + b2, -100.f), 100.f);
            v.w = fminf(fmaxf(c[rr][3] + b3, -100.f), 100.f);
            *(float4*)&outp[(size_t)m*D_MODEL + e0] = v;
        }
    }
}

// ---------------------------------------------------------------------------
// Flash attention. Block = (qtile=128 rows, head, batch). 128 threads:
// thread r owns one query row (q[64] + o[64] in registers).
// K/V streamed through smem in 16x64 tiles; uniform broadcast LDS.128 reads.
// Online softmax matches reference (clip +-50, key mask -10000, rowmax sub,
// denom + 1e-10; exp lower-clamp 1e-10 is <=2e-7 relative -> negligible).
// ---------------------------------------------------------------------------
__global__ __launch_bounds__(128, 2)
void nsattn_attn_kernel(const unsigned char* __restrict__ mask)
{
    const int qt = blockIdx.x;    // 0..15
    const int h  = blockIdx.y;    // 0..15
    const int b  = blockIdx.z;    // 0..3
    const int r  = threadIdx.x;   // 0..127

    const size_t headoff = ((size_t)(b*NHEAD + h))*SEQ*DK;
    const float* Qb = g_Q + headoff;
    const float* Kb = g_K + headoff;
    const float* Vb = g_V + headoff;
    const unsigned char* mb = mask + (size_t)b*SEQ;

    const int qrow = qt*128 + r;

    float4 q[16];
    {
        const float4* qp = (const float4*)(Qb + (size_t)qrow*DK);
        #pragma unroll
        for (int i=0;i<16;i++) q[i] = qp[i];
    }
    float4 o[16];
    #pragma unroll
    for (int i=0;i<16;i++) { o[i].x=0.f; o[i].y=0.f; o[i].z=0.f; o[i].w=0.f; }
    float mrun = -1e30f, lrun = 0.f;

    __shared__ float Ks[16*64];
    __shared__ float Vs[16*64];

    for (int kt = 0; kt < SEQ; kt += 16) {
        __syncthreads();
        {
            const float4* ksrc = (const float4*)(Kb + (size_t)kt*DK);
            const float4* vsrc = (const float4*)(Vb + (size_t)kt*DK);
            ((float4*)Ks)[r]       = ksrc[r];
            ((float4*)Ks)[r + 128] = ksrc[r + 128];
            ((float4*)Vs)[r]       = vsrc[r];
            ((float4*)Vs)[r + 128] = vsrc[r + 128];
        }
        __syncthreads();

        float s[16];
        float tmax = -1e30f;
        #pragma unroll
        for (int j = 0; j < 16; j++) {
            const float4* kr = (const float4*)(Ks + j*64);
            float acc = 0.f;
            #pragma unroll
            for (int i = 0; i < 16; i++) {
                float4 kv = kr[i];
                acc += q[i].x*kv.x + q[i].y*kv.y + q[i].z*kv.z + q[i].w*kv.w;
            }
            acc *= 0.125f;                                   // 1/sqrt(64)
            acc = fminf(fmaxf(acc, -50.f), 50.f);
            if (mb[kt + j]) acc = -10000.f;
            s[j] = acc;
            tmax = fmaxf(tmax, acc);
        }

        const float mnew = fmaxf(mrun, tmax);
        const float corr = __expf(mrun - mnew);
        lrun *= corr;
        #pragma unroll
        for (int i = 0; i < 16; i++) {
            o[i].x *= corr; o[i].y *= corr; o[i].z *= corr; o[i].w *= corr;
        }
        #pragma unroll
        for (int j = 0; j < 16; j++) {
            const float p = __expf(s[j] - mnew);
            lrun += p;
            const float4* vr = (const float4*)(Vs + j*64);
            #pragma unroll
            for (int i = 0; i < 16; i++) {
                float4 vv = vr[i];
                o[i].x += p*vv.x; o[i].y += p*vv.y; o[i].z += p*vv.z; o[i].w += p*vv.w;
            }
        }
        mrun = mnew;
    }

    const float inv = 1.f / (lrun + 1e-10f);
    float* outp = g_ctx + ((size_t)(b*SEQ + qrow))*D_MODEL + h*DK;
    #pragma unroll
    for (int i = 0; i < 16; i++) {
        float4 v;
        v.x = o[i].x*inv; v.y = o[i].y*inv; v.z = o[i].z*inv; v.w = o[i].w*inv;
        ((float4*)outp)[i] = v;
    }
}

// ---------------------------------------------------------------------------
extern "C" void kernel_launch(void* const* d_in, const int* in_sizes, int n_in,
                              void* d_out, int out_size)
{
    const float* x  = (const float*)d_in[0];
    const unsigned char* mask = (const unsigned char*)d_in[1];
    const float* Wq = (const float*)d_in[2];
    const float* bq = (const float*)d_in[3];
    const float* Wk = (const float*)d_in[4];
    const float* bk = (const float*)d_in[5];
    const float* Wv = (const float*)d_in[6];
    const float* bv = (const float*)d_in[7];
    const float* Wo = (const float*)d_in[8];
    const float* bo = (const float*)d_in[9];
    float* out = (float*)d_out;

    dim3 ggrid(D_MODEL/64, M_ROWS/64);   // (16, 128)

    nsattn_gemm_kernel<0><<<ggrid, 256>>>(x, Wq, bq, nullptr, D_MODEL, 1e-8f);
    nsattn_gemm_kernel<1><<<ggrid, 256>>>(x, Wk, bk, nullptr, D_MODEL, 1e-8f);
    nsattn_gemm_kernel<2><<<ggrid, 256>>>(x, Wv, bv, nullptr, D_MODEL, 1e-8f);

    nsattn_attn_kernel<<<dim3(SEQ/128, NHEAD, BATCH), 128>>>(mask);

    // WHICH==3 reads A = g_ctx directly in device code (never pass a
    // __device__ symbol from host).
    nsattn_gemm_kernel<3><<<ggrid, 256>>>(nullptr, Wo, bo, out, D_MODEL, 0.f);
}

// round 4
// speedup vs baseline: 1.4537x; 1.4537x over previous
#include <cuda_runtime.h>
#include <cuda_bf16.h>
#include <math.h>
#include <stdint.h>

#define D_MODEL 1024
#define NHEAD   16
#define DK      64
#define BATCH   4
#define SEQ     2048
#define M_ROWS  (BATCH*SEQ)   // 8192

// Scratch (static device globals; no runtime allocation)
__device__ float g_Q[BATCH*NHEAD*SEQ*DK];   // [B,H,T,dk]
__device__ float g_K[BATCH*NHEAD*SEQ*DK];
__device__ float g_V[BATCH*NHEAD*SEQ*DK];
__device__ float g_ctx[M_ROWS*D_MODEL];     // [B*T, D]

// ---------------------------------------------------------------------------
// Warp-level tensor-core primitives (portable: compile under compute_103)
// ---------------------------------------------------------------------------
__device__ __forceinline__ void ldmx4(uint32_t* r, uint32_t addr) {
    asm volatile("ldmatrix.sync.aligned.m8n8.x4.shared.b16 {%0,%1,%2,%3}, [%4];"
                 : "=r"(r[0]), "=r"(r[1]), "=r"(r[2]), "=r"(r[3]) : "r"(addr));
}

__device__ __forceinline__ void mma_bf16(float* d, const uint32_t* a,
                                         uint32_t b0, uint32_t b1) {
    asm volatile(
        "mma.sync.aligned.m16n8k16.row.col.f32.bf16.bf16.f32 "
        "{%0,%1,%2,%3}, {%4,%5,%6,%7}, {%8,%9}, {%0,%1,%2,%3};"
        : "+f"(d[0]), "+f"(d[1]), "+f"(d[2]), "+f"(d[3])
        : "r"(a[0]), "r"(a[1]), "r"(a[2]), "r"(a[3]), "r"(b0), "r"(b1));
}

__device__ __forceinline__ uint32_t smem_u32(const void* p) {
    uint32_t a;
    asm("{ .reg .u64 t; cvta.to.shared.u64 t, %1; cvt.u32.u64 %0, t; }"
        : "=r"(a) : "l"(p));
    return a;
}

// SW128 swizzle for 128-byte rows: XOR byte bits [6:4] with row bits [2:0]
__device__ __forceinline__ uint32_t sw128(uint32_t off) {
    return off ^ ((off >> 3) & 0x70);
}

// fp32x4 -> (hi bf16x4, lo bf16x4) packed as uint2 each
__device__ __forceinline__ void split4(float4 v, uint2& H, uint2& L) {
    __nv_bfloat16 hx = __float2bfloat16_rn(v.x);
    __nv_bfloat16 hy = __float2bfloat16_rn(v.y);
    __nv_bfloat16 hz = __float2bfloat16_rn(v.z);
    __nv_bfloat16 hw = __float2bfloat16_rn(v.w);
    __nv_bfloat162 h0 = __halves2bfloat162(hx, hy);
    __nv_bfloat162 h1 = __halves2bfloat162(hz, hw);
    __nv_bfloat16 lx = __float2bfloat16_rn(v.x - __bfloat162float(hx));
    __nv_bfloat16 ly = __float2bfloat16_rn(v.y - __bfloat162float(hy));
    __nv_bfloat16 lz = __float2bfloat16_rn(v.z - __bfloat162float(hz));
    __nv_bfloat16 lw = __float2bfloat16_rn(v.w - __bfloat162float(hw));
    __nv_bfloat162 l0 = __halves2bfloat162(lx, ly);
    __nv_bfloat162 l1 = __halves2bfloat162(lz, lw);
    H.x = *reinterpret_cast<uint32_t*>(&h0);
    H.y = *reinterpret_cast<uint32_t*>(&h1);
    L.x = *reinterpret_cast<uint32_t*>(&l0);
    L.y = *reinterpret_cast<uint32_t*>(&l1);
}

// ---------------------------------------------------------------------------
// HMMA GEMM (split-bf16 3-MMA, ~fp32 precision).
//   Y[m,e] = sum_k (A[m,k]+addA)*W[e,k] + bias[e], epilogue clip.
// CTA tile M=128, N=64, Kchunk=64; 8 warps as 4(M)x2(N), warp tile 32x32.
// QKV=true: grid.x in [0,48): which=bx>>4 selects Q/K/V; head-layout store,
//           clip +-10. QKV=false: A=g_ctx, row-major out, clip +-100.
// ---------------------------------------------------------------------------
template<bool QKV>
__global__ __launch_bounds__(256)
void hmma_gemm_kernel(const float* __restrict__ x,
                      const float* __restrict__ W0,
                      const float* __restrict__ W1,
                      const float* __restrict__ W2,
                      const float* __restrict__ b0v,
                      const float* __restrict__ b1v,
                      const float* __restrict__ b2v,
                      float* __restrict__ outp)
{
    __shared__ __align__(1024) unsigned char sAhi[128*128];  // 128 rows x 128B
    __shared__ __align__(1024) unsigned char sAlo[128*128];
    __shared__ __align__(1024) unsigned char sBhi[64*128];   // 64 rows x 128B
    __shared__ __align__(1024) unsigned char sBlo[64*128];

    const int tid  = threadIdx.x;
    const int wid  = tid >> 5;
    const int lane = tid & 31;
    const int mw   = wid & 3;        // M warp (0..3)
    const int nw   = wid >> 2;       // N warp (0..1)

    const int bx    = blockIdx.x;
    const int which = QKV ? (bx >> 4) : 3;
    const int n0    = (bx & 15) * 64;
    const int m0    = blockIdx.y * 128;

    const float* A    = QKV ? x : (const float*)g_ctx;
    const float* W    = QKV ? (which == 0 ? W0 : which == 1 ? W1 : W2) : W0;
    const float* bias = QKV ? (which == 0 ? b0v : which == 1 ? b1v : b2v) : b0v;
    const float addA  = QKV ? 1e-8f : 0.f;

    const uint32_t baseAhi = smem_u32(sAhi);
    const uint32_t baseAlo = smem_u32(sAlo);
    const uint32_t baseBhi = smem_u32(sBhi);
    const uint32_t baseBlo = smem_u32(sBlo);

    // Per-lane ldmatrix addressing (tile-static; hoisted by compiler):
    const int blk     = lane >> 3;
    const int rr      = lane & 7;
    // A: M0=rows0-7/k0-7, M1=rows8-15/k0-7, M2=rows0-7/k8-15, M3=rows8-15/k8-15
    const int aRowHalf = blk & 1;
    const int aKHalf   = blk >> 1;
    // B: M0=n0-7/k0-7, M1=n0-7/k8-15, M2=n8-15/k0-7, M3=n8-15/k8-15
    const int bNb      = blk >> 1;
    const int bKHalf   = blk & 1;

    float acc[2][4][4];
    #pragma unroll
    for (int i=0;i<2;i++)
        #pragma unroll
        for (int j=0;j<4;j++)
            #pragma unroll
            for (int l=0;l<4;l++) acc[i][j][l]=0.f;

    for (int chunk = 0; chunk < 16; chunk++) {
        const int k0 = chunk * 64;

        // Prefetch gmem into registers (before syncs, overlaps barrier wait)
        float4 va[8], vb[4];
        #pragma unroll
        for (int i = 0; i < 8; i++) {
            const int f = tid + i * 256;     // 0..2047
            va[i] = *(const float4*)(A + (size_t)(m0 + (f >> 4)) * D_MODEL + k0 + (f & 15) * 4);
        }
        #pragma unroll
        for (int i = 0; i < 4; i++) {
            const int f = tid + i * 256;     // 0..1023
            vb[i] = *(const float4*)(W + (size_t)(n0 + (f >> 4)) * D_MODEL + k0 + (f & 15) * 4);
        }

        __syncthreads();   // previous chunk's ldmatrix reads complete

        #pragma unroll
        for (int i = 0; i < 8; i++) {
            const int f   = tid + i * 256;
            const int row = f >> 4;
            const int c   = f & 15;
            float4 v = va[i];
            v.x += addA; v.y += addA; v.z += addA; v.w += addA;
            uint2 H, L;
            split4(v, H, L);
            const uint32_t sw = sw128((uint32_t)(row * 128 + c * 8));
            *(uint2*)(sAhi + sw) = H;
            *(uint2*)(sAlo + sw) = L;
        }
        #pragma unroll
        for (int i = 0; i < 4; i++) {
            const int f   = tid + i * 256;
            const int row = f >> 4;
            const int c   = f & 15;
            uint2 H, L;
            split4(vb[i], H, L);
            const uint32_t sw = sw128((uint32_t)(row * 128 + c * 8));
            *(uint2*)(sBhi + sw) = H;
            *(uint2*)(sBlo + sw) = L;
        }
        __syncthreads();

        #pragma unroll
        for (int ks = 0; ks < 4; ks++) {
            uint32_t ah[2][4], al[2][4];
            #pragma unroll
            for (int mf = 0; mf < 2; mf++) {
                const uint32_t row = (uint32_t)(mw*32 + mf*16 + aRowHalf*8 + rr);
                const uint32_t off = sw128(row * 128 + (uint32_t)(ks*16 + aKHalf*8) * 2);
                ldmx4(ah[mf], baseAhi + off);
                ldmx4(al[mf], baseAlo + off);
            }
            uint32_t bh[2][4], bl[2][4];
            #pragma unroll
            for (int pr = 0; pr < 2; pr++) {
                const uint32_t n   = (uint32_t)(nw*32 + pr*16 + bNb*8 + rr);
                const uint32_t off = sw128(n * 128 + (uint32_t)(ks*16 + bKHalf*8) * 2);
                ldmx4(bh[pr], baseBhi + off);
                ldmx4(bl[pr], baseBlo + off);
            }
            #pragma unroll
            for (int mf = 0; mf < 2; mf++) {
                #pragma unroll
                for (int nb = 0; nb < 4; nb++) {
                    const uint32_t B0h = bh[nb>>1][(nb&1)*2+0];
                    const uint32_t B1h = bh[nb>>1][(nb&1)*2+1];
                    const uint32_t B0l = bl[nb>>1][(nb&1)*2+0];
                    const uint32_t B1l = bl[nb>>1][(nb&1)*2+1];
                    mma_bf16(acc[mf][nb], ah[mf], B0h, B1h);
                    mma_bf16(acc[mf][nb], ah[mf], B0l, B1l);
                    mma_bf16(acc[mf][nb], al[mf], B0h, B1h);
                }
            }
        }
    }

    // Epilogue: bias + clip + store. Fragment c0,c1 -> (row, col..col+1),
    // c2,c3 -> (row+8, col..col+1); row=groupID, col=tg*2.
    const int gID = lane >> 2;
    const int tg  = lane & 3;
    const float clipv = (QKV && which < 3) ? 10.f : 100.f;

    #pragma unroll
    for (int mf = 0; mf < 2; mf++) {
        #pragma unroll
        for (int nb = 0; nb < 4; nb++) {
            const int colL = nw*32 + nb*8 + tg*2;
            const float bb0 = bias[n0 + colL];
            const float bb1 = bias[n0 + colL + 1];
            #pragma unroll
            for (int half = 0; half < 2; half++) {
                const int m = m0 + mw*32 + mf*16 + half*8 + gID;
                float2 v;
                v.x = fminf(fmaxf(acc[mf][nb][half*2+0] + bb0, -clipv), clipv);
                v.y = fminf(fmaxf(acc[mf][nb][half*2+1] + bb1, -clipv), clipv);
                if (QKV && which < 3) {
                    const int b_ = m >> 11;
                    const int t  = m & (SEQ - 1);
                    const int h  = bx & 15;
                    float* dst = (which == 0) ? g_Q : (which == 1) ? g_K : g_V;
                    *(float2*)(dst + (((size_t)(b_*NHEAD + h))*SEQ + t)*DK + colL) = v;
                } else {
                    *(float2*)(outp + (size_t)m * D_MODEL + n0 + colL) = v;
                }
            }
        }
    }
}

// ---------------------------------------------------------------------------
// Flash attention (unchanged; passing at rel_err 1.4e-6).
// ---------------------------------------------------------------------------
__global__ __launch_bounds__(128, 2)
void nsattn_attn_kernel(const unsigned char* __restrict__ mask)
{
    const int qt = blockIdx.x;
    const int h  = blockIdx.y;
    const int b  = blockIdx.z;
    const int r  = threadIdx.x;

    const size_t headoff = ((size_t)(b*NHEAD + h))*SEQ*DK;
    const float* Qb = g_Q + headoff;
    const float* Kb = g_K + headoff;
    const float* Vb = g_V + headoff;
    const unsigned char* mb = mask + (size_t)b*SEQ;

    const int qrow = qt*128 + r;

    float4 q[16];
    {
        const float4* qp = (const float4*)(Qb + (size_t)qrow*DK);
        #pragma unroll
        for (int i=0;i<16;i++) q[i] = qp[i];
    }
    float4 o[16];
    #pragma unroll
    for (int i=0;i<16;i++) { o[i].x=0.f; o[i].y=0.f; o[i].z=0.f; o[i].w=0.f; }
    float mrun = -1e30f, lrun = 0.f;

    __shared__ float Ks[16*64];
    __shared__ float Vs[16*64];

    for (int kt = 0; kt < SEQ; kt += 16) {
        __syncthreads();
        {
            const float4* ksrc = (const float4*)(Kb + (size_t)kt*DK);
            const float4* vsrc = (const float4*)(Vb + (size_t)kt*DK);
            ((float4*)Ks)[r]       = ksrc[r];
            ((float4*)Ks)[r + 128] = ksrc[r + 128];
            ((float4*)Vs)[r]       = vsrc[r];
            ((float4*)Vs)[r + 128] = vsrc[r + 128];
        }
        __syncthreads();

        float s[16];
        float tmax = -1e30f;
        #pragma unroll
        for (int j = 0; j < 16; j++) {
            const float4* kr = (const float4*)(Ks + j*64);
            float acc = 0.f;
            #pragma unroll
            for (int i = 0; i < 16; i++) {
                float4 kv = kr[i];
                acc += q[i].x*kv.x + q[i].y*kv.y + q[i].z*kv.z + q[i].w*kv.w;
            }
            acc *= 0.125f;
            acc = fminf(fmaxf(acc, -50.f), 50.f);
            if (mb[kt + j]) acc = -10000.f;
            s[j] = acc;
            tmax = fmaxf(tmax, acc);
        }

        const float mnew = fmaxf(mrun, tmax);
        const float corr = __expf(mrun - mnew);
        lrun *= corr;
        #pragma unroll
        for (int i = 0; i < 16; i++) {
            o[i].x *= corr; o[i].y *= corr; o[i].z *= corr; o[i].w *= corr;
        }
        #pragma unroll
        for (int j = 0; j < 16; j++) {
            const float p = __expf(s[j] - mnew);
            lrun += p;
            const float4* vr = (const float4*)(Vs + j*64);
            #pragma unroll
            for (int i = 0; i < 16; i++) {
                float4 vv = vr[i];
                o[i].x += p*vv.x; o[i].y += p*vv.y; o[i].z += p*vv.z; o[i].w += p*vv.w;
            }
        }
        mrun = mnew;
    }

    const float inv = 1.f / (lrun + 1e-10f);
    float* outp = g_ctx + ((size_t)(b*SEQ + qrow))*D_MODEL + h*DK;
    #pragma unroll
    for (int i = 0; i < 16; i++) {
        float4 v;
        v.x = o[i].x*inv; v.y = o[i].y*inv; v.z = o[i].z*inv; v.w = o[i].w*inv;
        ((float4*)outp)[i] = v;
    }
}

// ---------------------------------------------------------------------------
extern "C" void kernel_launch(void* const* d_in, const int* in_sizes, int n_in,
                              void* d_out, int out_size)
{
    const float* x  = (const float*)d_in[0];
    const unsigned char* mask = (const unsigned char*)d_in[1];
    const float* Wq = (const float*)d_in[2];
    const float* bq = (const float*)d_in[3];
    const float* Wk = (const float*)d_in[4];
    const float* bk = (const float*)d_in[5];
    const float* Wv = (const float*)d_in[6];
    const float* bv = (const float*)d_in[7];
    const float* Wo = (const float*)d_in[8];
    const float* bo = (const float*)d_in[9];
    float* out = (float*)d_out;

    // Fused Q/K/V projections (grid.x: [0,16)=Q, [16,32)=K, [32,48)=V)
    hmma_gemm_kernel<true><<<dim3(48, M_ROWS/128), 256>>>(
        x, Wq, Wk, Wv, bq, bk, bv, nullptr);

    nsattn_attn_kernel<<<dim3(SEQ/128, NHEAD, BATCH), 128>>>(mask);

    // Output projection (A = g_ctx read in device code)
    hmma_gemm_kernel<false><<<dim3(16, M_ROWS/128), 256>>>(
        nullptr, Wo, Wo, Wo, bo, bo, bo, out);
}

// round 5
// speedup vs baseline: 3.1034x; 2.1348x over previous
#include <cuda_runtime.h>
#include <cuda_bf16.h>
#include <math.h>
#include <stdint.h>

#define D_MODEL 1024
#define NHEAD   16
#define DK      64
#define BATCH   4
#define SEQ     2048
#define M_ROWS  (BATCH*SEQ)   // 8192

// Scratch (static device globals; no runtime allocation)
__device__ float g_Q[BATCH*NHEAD*SEQ*DK];   // [B,H,T,dk]
__device__ float g_K[BATCH*NHEAD*SEQ*DK];
__device__ float g_V[BATCH*NHEAD*SEQ*DK];
__device__ float g_ctx[M_ROWS*D_MODEL];     // [B*T, D]

// ---------------------------------------------------------------------------
// Warp-level tensor-core primitives (portable under compute_103)
// ---------------------------------------------------------------------------
__device__ __forceinline__ void ldmx4(uint32_t* r, uint32_t addr) {
    asm volatile("ldmatrix.sync.aligned.m8n8.x4.shared.b16 {%0,%1,%2,%3}, [%4];"
                 : "=r"(r[0]), "=r"(r[1]), "=r"(r[2]), "=r"(r[3]) : "r"(addr));
}

__device__ __forceinline__ void mma_bf16(float* d, const uint32_t* a,
                                         uint32_t b0, uint32_t b1) {
    asm volatile(
        "mma.sync.aligned.m16n8k16.row.col.f32.bf16.bf16.f32 "
        "{%0,%1,%2,%3}, {%4,%5,%6,%7}, {%8,%9}, {%0,%1,%2,%3};"
        : "+f"(d[0]), "+f"(d[1]), "+f"(d[2]), "+f"(d[3])
        : "r"(a[0]), "r"(a[1]), "r"(a[2]), "r"(a[3]), "r"(b0), "r"(b1));
}

__device__ __forceinline__ uint32_t smem_u32(const void* p) {
    uint32_t a;
    asm("{ .reg .u64 t; cvta.to.shared.u64 t, %1; cvt.u32.u64 %0, t; }"
        : "=r"(a) : "l"(p));
    return a;
}

__device__ __forceinline__ uint32_t sw128(uint32_t off) {
    return off ^ ((off >> 3) & 0x70);
}

__device__ __forceinline__ unsigned short bf16bits(float f) {
    __nv_bfloat16 h = __float2bfloat16_rn(f);
    return *reinterpret_cast<unsigned short*>(&h);
}

// fp32x4 -> (hi bf16x4, lo bf16x4) packed as uint2 each
__device__ __forceinline__ void split4(float4 v, uint2& H, uint2& L) {
    __nv_bfloat16 hx = __float2bfloat16_rn(v.x);
    __nv_bfloat16 hy = __float2bfloat16_rn(v.y);
    __nv_bfloat16 hz = __float2bfloat16_rn(v.z);
    __nv_bfloat16 hw = __float2bfloat16_rn(v.w);
    __nv_bfloat162 h0 = __halves2bfloat162(hx, hy);
    __nv_bfloat162 h1 = __halves2bfloat162(hz, hw);
    __nv_bfloat16 lx = __float2bfloat16_rn(v.x - __bfloat162float(hx));
    __nv_bfloat16 ly = __float2bfloat16_rn(v.y - __bfloat162float(hy));
    __nv_bfloat16 lz = __float2bfloat16_rn(v.z - __bfloat162float(hz));
    __nv_bfloat16 lw = __float2bfloat16_rn(v.w - __bfloat162float(hw));
    __nv_bfloat162 l0 = __halves2bfloat162(lx, ly);
    __nv_bfloat162 l1 = __halves2bfloat162(lz, lw);
    H.x = *reinterpret_cast<uint32_t*>(&h0);
    H.y = *reinterpret_cast<uint32_t*>(&h1);
    L.x = *reinterpret_cast<uint32_t*>(&l0);
    L.y = *reinterpret_cast<uint32_t*>(&l1);
}

// pack two floats into bf16x2 (lo = first), returning hi-part and lo-part words
__device__ __forceinline__ void split_pack2(float a, float b, uint32_t& H, uint32_t& L) {
    unsigned short ha = bf16bits(a), hb = bf16bits(b);
    float fa, fb;
    { __nv_bfloat16 t = *reinterpret_cast<__nv_bfloat16*>(&ha); fa = __bfloat162float(t); }
    { __nv_bfloat16 t = *reinterpret_cast<__nv_bfloat16*>(&hb); fb = __bfloat162float(t); }
    unsigned short la = bf16bits(a - fa), lb = bf16bits(b - fb);
    H = (uint32_t)ha | ((uint32_t)hb << 16);
    L = (uint32_t)la | ((uint32_t)lb << 16);
}

// ---------------------------------------------------------------------------
// HMMA GEMM (split-bf16 3-MMA) — unchanged from R4 (passing, 472us QKV).
// ---------------------------------------------------------------------------
template<bool QKV>
__global__ __launch_bounds__(256)
void hmma_gemm_kernel(const float* __restrict__ x,
                      const float* __restrict__ W0,
                      const float* __restrict__ W1,
                      const float* __restrict__ W2,
                      const float* __restrict__ b0v,
                      const float* __restrict__ b1v,
                      const float* __restrict__ b2v,
                      float* __restrict__ outp)
{
    __shared__ __align__(1024) unsigned char sAhi[128*128];
    __shared__ __align__(1024) unsigned char sAlo[128*128];
    __shared__ __align__(1024) unsigned char sBhi[64*128];
    __shared__ __align__(1024) unsigned char sBlo[64*128];

    const int tid  = threadIdx.x;
    const int wid  = tid >> 5;
    const int lane = tid & 31;
    const int mw   = wid & 3;
    const int nw   = wid >> 2;

    const int bx    = blockIdx.x;
    const int which = QKV ? (bx >> 4) : 3;
    const int n0    = (bx & 15) * 64;
    const int m0    = blockIdx.y * 128;

    const float* A    = QKV ? x : (const float*)g_ctx;
    const float* W    = QKV ? (which == 0 ? W0 : which == 1 ? W1 : W2) : W0;
    const float* bias = QKV ? (which == 0 ? b0v : which == 1 ? b1v : b2v) : b0v;
    const float addA  = QKV ? 1e-8f : 0.f;

    const uint32_t baseAhi = smem_u32(sAhi);
    const uint32_t baseAlo = smem_u32(sAlo);
    const uint32_t baseBhi = smem_u32(sBhi);
    const uint32_t baseBlo = smem_u32(sBlo);

    const int blk      = lane >> 3;
    const int rr       = lane & 7;
    const int aRowHalf = blk & 1;
    const int aKHalf   = blk >> 1;
    const int bNb      = blk >> 1;
    const int bKHalf   = blk & 1;

    float acc[2][4][4];
    #pragma unroll
    for (int i=0;i<2;i++)
        #pragma unroll
        for (int j=0;j<4;j++)
            #pragma unroll
            for (int l=0;l<4;l++) acc[i][j][l]=0.f;

    for (int chunk = 0; chunk < 16; chunk++) {
        const int k0 = chunk * 64;

        float4 va[8], vb[4];
        #pragma unroll
        for (int i = 0; i < 8; i++) {
            const int f = tid + i * 256;
            va[i] = *(const float4*)(A + (size_t)(m0 + (f >> 4)) * D_MODEL + k0 + (f & 15) * 4);
        }
        #pragma unroll
        for (int i = 0; i < 4; i++) {
            const int f = tid + i * 256;
            vb[i] = *(const float4*)(W + (size_t)(n0 + (f >> 4)) * D_MODEL + k0 + (f & 15) * 4);
        }

        __syncthreads();

        #pragma unroll
        for (int i = 0; i < 8; i++) {
            const int f   = tid + i * 256;
            const int row = f >> 4;
            const int c   = f & 15;
            float4 v = va[i];
            v.x += addA; v.y += addA; v.z += addA; v.w += addA;
            uint2 H, L;
            split4(v, H, L);
            const uint32_t sw = sw128((uint32_t)(row * 128 + c * 8));
            *(uint2*)(sAhi + sw) = H;
            *(uint2*)(sAlo + sw) = L;
        }
        #pragma unroll
        for (int i = 0; i < 4; i++) {
            const int f   = tid + i * 256;
            const int row = f >> 4;
            const int c   = f & 15;
            uint2 H, L;
            split4(vb[i], H, L);
            const uint32_t sw = sw128((uint32_t)(row * 128 + c * 8));
            *(uint2*)(sBhi + sw) = H;
            *(uint2*)(sBlo + sw) = L;
        }
        __syncthreads();

        #pragma unroll
        for (int ks = 0; ks < 4; ks++) {
            uint32_t ah[2][4], al[2][4];
            #pragma unroll
            for (int mf = 0; mf < 2; mf++) {
                const uint32_t row = (uint32_t)(mw*32 + mf*16 + aRowHalf*8 + rr);
                const uint32_t off = sw128(row * 128 + (uint32_t)(ks*16 + aKHalf*8) * 2);
                ldmx4(ah[mf], baseAhi + off);
                ldmx4(al[mf], baseAlo + off);
            }
            uint32_t bh[2][4], bl[2][4];
            #pragma unroll
            for (int pr = 0; pr < 2; pr++) {
                const uint32_t n   = (uint32_t)(nw*32 + pr*16 + bNb*8 + rr);
                const uint32_t off = sw128(n * 128 + (uint32_t)(ks*16 + bKHalf*8) * 2);
                ldmx4(bh[pr], baseBhi + off);
                ldmx4(bl[pr], baseBlo + off);
            }
            #pragma unroll
            for (int mf = 0; mf < 2; mf++) {
                #pragma unroll
                for (int nb = 0; nb < 4; nb++) {
                    const uint32_t B0h = bh[nb>>1][(nb&1)*2+0];
                    const uint32_t B1h = bh[nb>>1][(nb&1)*2+1];
                    const uint32_t B0l = bl[nb>>1][(nb&1)*2+0];
                    const uint32_t B1l = bl[nb>>1][(nb&1)*2+1];
                    mma_bf16(acc[mf][nb], ah[mf], B0h, B1h);
                    mma_bf16(acc[mf][nb], ah[mf], B0l, B1l);
                    mma_bf16(acc[mf][nb], al[mf], B0h, B1h);
                }
            }
        }
    }

    const int gID = lane >> 2;
    const int tg  = lane & 3;
    const float clipv = (QKV && which < 3) ? 10.f : 100.f;

    #pragma unroll
    for (int mf = 0; mf < 2; mf++) {
        #pragma unroll
        for (int nb = 0; nb < 4; nb++) {
            const int colL = nw*32 + nb*8 + tg*2;
            const float bb0 = bias[n0 + colL];
            const float bb1 = bias[n0 + colL + 1];
            #pragma unroll
            for (int half = 0; half < 2; half++) {
                const int m = m0 + mw*32 + mf*16 + half*8 + gID;
                float2 v;
                v.x = fminf(fmaxf(acc[mf][nb][half*2+0] + bb0, -clipv), clipv);
                v.y = fminf(fmaxf(acc[mf][nb][half*2+1] + bb1, -clipv), clipv);
                if (QKV && which < 3) {
                    const int b_ = m >> 11;
                    const int t  = m & (SEQ - 1);
                    const int h  = bx & 15;
                    float* dst = (which == 0) ? g_Q : (which == 1) ? g_K : g_V;
                    *(float2*)(dst + (((size_t)(b_*NHEAD + h))*SEQ + t)*DK + colL) = v;
                } else {
                    *(float2*)(outp + (size_t)m * D_MODEL + n0 + colL) = v;
                }
            }
        }
    }
}

// ---------------------------------------------------------------------------
// HMMA flash attention. CTA = 128 q-rows x (head, batch). 8 warps, each owns
// 16 q-rows x all 64 keys/d. Split-bf16 3-MMA for QK^T and PV. smem overlay:
//   phase 0: [0,16K)=Qhi [16K,32K)=Qlo   (Q -> register A-fragments)
//   per kt : [0,8K)=Khi [8K,16K)=Klo [16K,24K)=VThi [24K,32K)=VTlo
// VT stored transposed (rows=d, cols=key) so PV B uses the validated
// non-trans ldmatrix path.
// ---------------------------------------------------------------------------
__global__ __launch_bounds__(256, 1)
void attn_hmma_kernel(const unsigned char* __restrict__ mask)
{
    __shared__ __align__(1024) unsigned char sbuf[32768];
    __shared__ unsigned char smask[64];

    const int tid  = threadIdx.x;
    const int wid  = tid >> 5;
    const int lane = tid & 31;
    const int gID  = lane >> 2;
    const int tg   = lane & 3;

    const int blk      = lane >> 3;
    const int rr       = lane & 7;
    const int aRowHalf = blk & 1;
    const int aKHalf   = blk >> 1;
    const int bNb      = blk >> 1;
    const int bKHalf   = blk & 1;

    const int qt = blockIdx.x;     // 0..15
    const int h  = blockIdx.y;     // 0..15
    const int b  = blockIdx.z;     // 0..3
    const int m0 = qt * 128;

    const size_t headoff = ((size_t)(b*NHEAD + h))*SEQ*DK;
    const float* Qb = g_Q + headoff;
    const float* Kb = g_K + headoff;
    const float* Vb = g_V + headoff;
    const unsigned char* mb = mask + (size_t)b*SEQ;

    const uint32_t sb = smem_u32(sbuf);

    // ---- Phase 0: Q tile 128x64 -> split bf16 -> smem, then to registers
    #pragma unroll
    for (int i = 0; i < 8; i++) {
        const int f   = tid + i * 256;
        const int row = f >> 4;
        const int c   = f & 15;
        float4 v = *(const float4*)(Qb + (size_t)(m0 + row) * DK + c * 4);
        uint2 H, L;
        split4(v, H, L);
        const uint32_t sw = sw128((uint32_t)(row * 128 + c * 8));
        *(uint2*)(sbuf + sw)         = H;   // Qhi at 0
        *(uint2*)(sbuf + 16384 + sw) = L;   // Qlo at 16K
    }
    __syncthreads();

    uint32_t qh[4][4], ql[4][4];
    #pragma unroll
    for (int ks = 0; ks < 4; ks++) {
        const uint32_t row = (uint32_t)(wid*16 + aRowHalf*8 + rr);
        const uint32_t off = sw128(row * 128 + (uint32_t)(ks*16 + aKHalf*8) * 2);
        ldmx4(qh[ks], sb + off);
        ldmx4(ql[ks], sb + 16384 + off);
    }
    __syncthreads();   // Q smem now dead; overlay with K/VT

    float oacc[8][4];
    #pragma unroll
    for (int nb = 0; nb < 8; nb++)
        #pragma unroll
        for (int i = 0; i < 4; i++) oacc[nb][i] = 0.f;
    float mrun0 = -1e30f, mrun1 = -1e30f;
    float lrun0 = 0.f,    lrun1 = 0.f;

    for (int kt = 0; kt < SEQ; kt += 64) {
        // ---- fill K (rows=key) and VT (rows=d, transposed) + mask bytes
        #pragma unroll
        for (int i = 0; i < 4; i++) {
            const int f   = tid + i * 256;
            const int row = f >> 4;           // key 0..63
            const int c   = f & 15;
            float4 v = *(const float4*)(Kb + (size_t)(kt + row) * DK + c * 4);
            uint2 H, L;
            split4(v, H, L);
            const uint32_t sw = sw128((uint32_t)(row * 128 + c * 8));
            *(uint2*)(sbuf + sw)        = H;   // Khi at 0
            *(uint2*)(sbuf + 8192 + sw) = L;   // Klo at 8K
        }
        #pragma unroll
        for (int i = 0; i < 4; i++) {
            const int f   = tid + i * 256;
            const int row = f >> 4;           // key 0..63
            const int c   = f & 15;
            float4 v = *(const float4*)(Vb + (size_t)(kt + row) * DK + c * 4);
            float vv[4] = {v.x, v.y, v.z, v.w};
            #pragma unroll
            for (int j = 0; j < 4; j++) {
                unsigned short hb = bf16bits(vv[j]);
                float hf;
                { __nv_bfloat16 t = *reinterpret_cast<__nv_bfloat16*>(&hb); hf = __bfloat162float(t); }
                unsigned short lb = bf16bits(vv[j] - hf);
                const uint32_t sw = sw128((uint32_t)((c*4 + j) * 128 + row * 2));
                *(unsigned short*)(sbuf + 16384 + sw) = hb;   // VThi at 16K
                *(unsigned short*)(sbuf + 24576 + sw) = lb;   // VTlo at 24K
            }
        }
        if (tid < 16) ((uint32_t*)smask)[tid] = *(const uint32_t*)(mb + kt + tid*4);
        __syncthreads();

        // ---- QK^T: scores 16q x 64keys per warp
        float sacc[8][4];
        #pragma unroll
        for (int nt = 0; nt < 8; nt++)
            #pragma unroll
            for (int i = 0; i < 4; i++) sacc[nt][i] = 0.f;

        #pragma unroll
        for (int kg = 0; kg < 4; kg++) {          // 16-key groups
            #pragma unroll
            for (int ks = 0; ks < 4; ks++) {      // d-steps of 16
                uint32_t bh[4], bl[4];
                const uint32_t row = (uint32_t)(kg*16 + bNb*8 + rr);
                const uint32_t off = sw128(row * 128 + (uint32_t)(ks*16 + bKHalf*8) * 2);
                ldmx4(bh, sb + off);
                ldmx4(bl, sb + 8192 + off);
                #pragma unroll
                for (int sub = 0; sub < 2; sub++) {
                    const int nt = kg*2 + sub;
                    mma_bf16(sacc[nt], qh[ks], bh[sub*2], bh[sub*2+1]);
                    mma_bf16(sacc[nt], qh[ks], bl[sub*2], bl[sub*2+1]);
                    mma_bf16(sacc[nt], ql[ks], bh[sub*2], bh[sub*2+1]);
                }
            }
        }

        // ---- scale, clip, mask
        #pragma unroll
        for (int nt = 0; nt < 8; nt++) {
            const int keyc = nt*8 + tg*2;
            const bool f0 = smask[keyc] != 0;
            const bool f1 = smask[keyc + 1] != 0;
            #pragma unroll
            for (int i = 0; i < 4; i++) {
                float s = fminf(fmaxf(sacc[nt][i] * 0.125f, -50.f), 50.f);
                if ((i & 1) ? f1 : f0) s = -10000.f;
                sacc[nt][i] = s;
            }
        }

        // ---- online softmax (rows gID and gID+8)
        float tmax0 = -1e30f, tmax1 = -1e30f;
        #pragma unroll
        for (int nt = 0; nt < 8; nt++) {
            tmax0 = fmaxf(tmax0, fmaxf(sacc[nt][0], sacc[nt][1]));
            tmax1 = fmaxf(tmax1, fmaxf(sacc[nt][2], sacc[nt][3]));
        }
        tmax0 = fmaxf(tmax0, __shfl_xor_sync(0xffffffffu, tmax0, 1));
        tmax0 = fmaxf(tmax0, __shfl_xor_sync(0xffffffffu, tmax0, 2));
        tmax1 = fmaxf(tmax1, __shfl_xor_sync(0xffffffffu, tmax1, 1));
        tmax1 = fmaxf(tmax1, __shfl_xor_sync(0xffffffffu, tmax1, 2));

        const float mnew0 = fmaxf(mrun0, tmax0);
        const float mnew1 = fmaxf(mrun1, tmax1);
        const float corr0 = __expf(mrun0 - mnew0);
        const float corr1 = __expf(mrun1 - mnew1);
        mrun0 = mnew0; mrun1 = mnew1;
        #pragma unroll
        for (int nb = 0; nb < 8; nb++) {
            oacc[nb][0] *= corr0; oacc[nb][1] *= corr0;
            oacc[nb][2] *= corr1; oacc[nb][3] *= corr1;
        }

        // ---- p = exp(s - m): pack to PV A-fragments (hi/lo)
        uint32_t pah[4][4], pal[4][4];
        float rs0 = 0.f, rs1 = 0.f;
        #pragma unroll
        for (int ks = 0; ks < 4; ks++) {
            #pragma unroll
            for (int sub = 0; sub < 2; sub++) {
                const int nt = ks*2 + sub;
                const float p0 = __expf(sacc[nt][0] - mnew0);
                const float p1 = __expf(sacc[nt][1] - mnew0);
                const float p2 = __expf(sacc[nt][2] - mnew1);
                const float p3 = __expf(sacc[nt][3] - mnew1);
                rs0 += p0 + p1;
                rs1 += p2 + p3;
                split_pack2(p0, p1, pah[ks][sub*2+0], pal[ks][sub*2+0]);
                split_pack2(p2, p3, pah[ks][sub*2+1], pal[ks][sub*2+1]);
            }
        }
        rs0 += __shfl_xor_sync(0xffffffffu, rs0, 1);
        rs0 += __shfl_xor_sync(0xffffffffu, rs0, 2);
        rs1 += __shfl_xor_sync(0xffffffffu, rs1, 1);
        rs1 += __shfl_xor_sync(0xffffffffu, rs1, 2);
        lrun0 = lrun0 * corr0 + rs0;
        lrun1 = lrun1 * corr1 + rs1;

        // ---- PV: out += P(16x64) * V(64keys x 64d), B from VT (rows=d)
        #pragma unroll
        for (int dg = 0; dg < 4; dg++) {          // 16-d groups
            #pragma unroll
            for (int ks = 0; ks < 4; ks++) {      // key-steps of 16
                uint32_t vh[4], vl[4];
                const uint32_t row = (uint32_t)(dg*16 + bNb*8 + rr);
                const uint32_t off = sw128(row * 128 + (uint32_t)(ks*16 + bKHalf*8) * 2);
                ldmx4(vh, sb + 16384 + off);
                ldmx4(vl, sb + 24576 + off);
                #pragma unroll
                for (int sub = 0; sub < 2; sub++) {
                    const int nb = dg*2 + sub;
                    mma_bf16(oacc[nb], pah[ks], vh[sub*2], vh[sub*2+1]);
                    mma_bf16(oacc[nb], pah[ks], vl[sub*2], vl[sub*2+1]);
                    mma_bf16(oacc[nb], pal[ks], vh[sub*2], vh[sub*2+1]);
                }
            }
        }
        __syncthreads();   // tile consumed; next iteration overwrites smem
    }

    // ---- normalize + store to g_ctx [B*T, D] at column h*64
    const float inv0 = 1.f / (lrun0 + 1e-10f);
    const float inv1 = 1.f / (lrun1 + 1e-10f);
    const int row0 = m0 + wid*16 + gID;
    const int row1 = row0 + 8;
    float* c0 = g_ctx + ((size_t)(b*SEQ + row0))*D_MODEL + h*DK;
    float* c1 = g_ctx + ((size_t)(b*SEQ + row1))*D_MODEL + h*DK;
    #pragma unroll
    for (int nb = 0; nb < 8; nb++) {
        const int col = nb*8 + tg*2;
        float2 v0, v1;
        v0.x = oacc[nb][0]*inv0; v0.y = oacc[nb][1]*inv0;
        v1.x = oacc[nb][2]*inv1; v1.y = oacc[nb][3]*inv1;
        *(float2*)(c0 + col) = v0;
        *(float2*)(c1 + col) = v1;
    }
}

// ---------------------------------------------------------------------------
extern "C" void kernel_launch(void* const* d_in, const int* in_sizes, int n_in,
                              void* d_out, int out_size)
{
    const float* x  = (const float*)d_in[0];
    const unsigned char* mask = (const unsigned char*)d_in[1];
    const float* Wq = (const float*)d_in[2];
    const float* bq = (const float*)d_in[3];
    const float* Wk = (const float*)d_in[4];
    const float* bk = (const float*)d_in[5];
    const float* Wv = (const float*)d_in[6];
    const float* bv = (const float*)d_in[7];
    const float* Wo = (const float*)d_in[8];
    const float* bo = (const float*)d_in[9];
    float* out = (float*)d_out;

    hmma_gemm_kernel<true><<<dim3(48, M_ROWS/128), 256>>>(
        x, Wq, Wk, Wv, bq, bk, bv, nullptr);

    attn_hmma_kernel<<<dim3(SEQ/128, NHEAD, BATCH), 256>>>(mask);

    hmma_gemm_kernel<false><<<dim3(16, M_ROWS/128), 256>>>(
        nullptr, Wo, Wo, Wo, bo, bo, bo, out);
}

// round 6
// speedup vs baseline: 3.6627x; 1.1802x over previous
#include <cuda_runtime.h>
#include <cuda_bf16.h>
#include <math.h>
#include <stdint.h>

#define D_MODEL 1024
#define NHEAD   16
#define DK      64
#define BATCH   4
#define SEQ     2048
#define M_ROWS  (BATCH*SEQ)   // 8192

// Scratch (static device globals; no runtime allocation)
__device__ float g_Q[BATCH*NHEAD*SEQ*DK];   // [B,H,T,dk]
__device__ float g_K[BATCH*NHEAD*SEQ*DK];
__device__ float g_V[BATCH*NHEAD*SEQ*DK];
__device__ float g_ctx[M_ROWS*D_MODEL];     // [B*T, D]

// ---------------------------------------------------------------------------
// Warp-level tensor-core primitives (portable under compute_103)
// ---------------------------------------------------------------------------
__device__ __forceinline__ void ldmx4(uint32_t* r, uint32_t addr) {
    asm volatile("ldmatrix.sync.aligned.m8n8.x4.shared.b16 {%0,%1,%2,%3}, [%4];"
                 : "=r"(r[0]), "=r"(r[1]), "=r"(r[2]), "=r"(r[3]) : "r"(addr));
}

__device__ __forceinline__ void ldmx4t(uint32_t* r, uint32_t addr) {
    asm volatile("ldmatrix.sync.aligned.m8n8.x4.trans.shared.b16 {%0,%1,%2,%3}, [%4];"
                 : "=r"(r[0]), "=r"(r[1]), "=r"(r[2]), "=r"(r[3]) : "r"(addr));
}

__device__ __forceinline__ void mma_bf16(float* d, const uint32_t* a,
                                         uint32_t b0, uint32_t b1) {
    asm volatile(
        "mma.sync.aligned.m16n8k16.row.col.f32.bf16.bf16.f32 "
        "{%0,%1,%2,%3}, {%4,%5,%6,%7}, {%8,%9}, {%0,%1,%2,%3};"
        : "+f"(d[0]), "+f"(d[1]), "+f"(d[2]), "+f"(d[3])
        : "r"(a[0]), "r"(a[1]), "r"(a[2]), "r"(a[3]), "r"(b0), "r"(b1));
}

__device__ __forceinline__ uint32_t smem_u32(const void* p) {
    uint32_t a;
    asm("{ .reg .u64 t; cvta.to.shared.u64 t, %1; cvt.u32.u64 %0, t; }"
        : "=r"(a) : "l"(p));
    return a;
}

__device__ __forceinline__ uint32_t sw128(uint32_t off) {
    return off ^ ((off >> 3) & 0x70);
}

__device__ __forceinline__ unsigned short bf16bits(float f) {
    __nv_bfloat16 h = __float2bfloat16_rn(f);
    return *reinterpret_cast<unsigned short*>(&h);
}

// fp32x4 -> (hi bf16x4, lo bf16x4) packed as uint2 each
__device__ __forceinline__ void split4(float4 v, uint2& H, uint2& L) {
    __nv_bfloat16 hx = __float2bfloat16_rn(v.x);
    __nv_bfloat16 hy = __float2bfloat16_rn(v.y);
    __nv_bfloat16 hz = __float2bfloat16_rn(v.z);
    __nv_bfloat16 hw = __float2bfloat16_rn(v.w);
    __nv_bfloat162 h0 = __halves2bfloat162(hx, hy);
    __nv_bfloat162 h1 = __halves2bfloat162(hz, hw);
    __nv_bfloat16 lx = __float2bfloat16_rn(v.x - __bfloat162float(hx));
    __nv_bfloat16 ly = __float2bfloat16_rn(v.y - __bfloat162float(hy));
    __nv_bfloat16 lz = __float2bfloat16_rn(v.z - __bfloat162float(hz));
    __nv_bfloat16 lw = __float2bfloat16_rn(v.w - __bfloat162float(hw));
    __nv_bfloat162 l0 = __halves2bfloat162(lx, ly);
    __nv_bfloat162 l1 = __halves2bfloat162(lz, lw);
    H.x = *reinterpret_cast<uint32_t*>(&h0);
    H.y = *reinterpret_cast<uint32_t*>(&h1);
    L.x = *reinterpret_cast<uint32_t*>(&l0);
    L.y = *reinterpret_cast<uint32_t*>(&l1);
}

// pack two floats into bf16x2, returning hi-part and lo-part words
__device__ __forceinline__ void split_pack2(float a, float b, uint32_t& H, uint32_t& L) {
    unsigned short ha = bf16bits(a), hb = bf16bits(b);
    float fa, fb;
    { __nv_bfloat16 t = *reinterpret_cast<__nv_bfloat16*>(&ha); fa = __bfloat162float(t); }
    { __nv_bfloat16 t = *reinterpret_cast<__nv_bfloat16*>(&hb); fb = __bfloat162float(t); }
    unsigned short la = bf16bits(a - fa), lb = bf16bits(b - fb);
    H = (uint32_t)ha | ((uint32_t)hb << 16);
    L = (uint32_t)la | ((uint32_t)lb << 16);
}

// ---------------------------------------------------------------------------
// HMMA GEMM (split-bf16 3-MMA) — unchanged (passing, 471us QKV / 157us Oproj).
// ---------------------------------------------------------------------------
template<bool QKV>
__global__ __launch_bounds__(256)
void hmma_gemm_kernel(const float* __restrict__ x,
                      const float* __restrict__ W0,
                      const float* __restrict__ W1,
                      const float* __restrict__ W2,
                      const float* __restrict__ b0v,
                      const float* __restrict__ b1v,
                      const float* __restrict__ b2v,
                      float* __restrict__ outp)
{
    __shared__ __align__(1024) unsigned char sAhi[128*128];
    __shared__ __align__(1024) unsigned char sAlo[128*128];
    __shared__ __align__(1024) unsigned char sBhi[64*128];
    __shared__ __align__(1024) unsigned char sBlo[64*128];

    const int tid  = threadIdx.x;
    const int wid  = tid >> 5;
    const int lane = tid & 31;
    const int mw   = wid & 3;
    const int nw   = wid >> 2;

    const int bx    = blockIdx.x;
    const int which = QKV ? (bx >> 4) : 3;
    const int n0    = (bx & 15) * 64;
    const int m0    = blockIdx.y * 128;

    const float* A    = QKV ? x : (const float*)g_ctx;
    const float* W    = QKV ? (which == 0 ? W0 : which == 1 ? W1 : W2) : W0;
    const float* bias = QKV ? (which == 0 ? b0v : which == 1 ? b1v : b2v) : b0v;
    const float addA  = QKV ? 1e-8f : 0.f;

    const uint32_t baseAhi = smem_u32(sAhi);
    const uint32_t baseAlo = smem_u32(sAlo);
    const uint32_t baseBhi = smem_u32(sBhi);
    const uint32_t baseBlo = smem_u32(sBlo);

    const int blk      = lane >> 3;
    const int rr       = lane & 7;
    const int aRowHalf = blk & 1;
    const int aKHalf   = blk >> 1;
    const int bNb      = blk >> 1;
    const int bKHalf   = blk & 1;

    float acc[2][4][4];
    #pragma unroll
    for (int i=0;i<2;i++)
        #pragma unroll
        for (int j=0;j<4;j++)
            #pragma unroll
            for (int l=0;l<4;l++) acc[i][j][l]=0.f;

    for (int chunk = 0; chunk < 16; chunk++) {
        const int k0 = chunk * 64;

        float4 va[8], vb[4];
        #pragma unroll
        for (int i = 0; i < 8; i++) {
            const int f = tid + i * 256;
            va[i] = *(const float4*)(A + (size_t)(m0 + (f >> 4)) * D_MODEL + k0 + (f & 15) * 4);
        }
        #pragma unroll
        for (int i = 0; i < 4; i++) {
            const int f = tid + i * 256;
            vb[i] = *(const float4*)(W + (size_t)(n0 + (f >> 4)) * D_MODEL + k0 + (f & 15) * 4);
        }

        __syncthreads();

        #pragma unroll
        for (int i = 0; i < 8; i++) {
            const int f   = tid + i * 256;
            const int row = f >> 4;
            const int c   = f & 15;
            float4 v = va[i];
            v.x += addA; v.y += addA; v.z += addA; v.w += addA;
            uint2 H, L;
            split4(v, H, L);
            const uint32_t sw = sw128((uint32_t)(row * 128 + c * 8));
            *(uint2*)(sAhi + sw) = H;
            *(uint2*)(sAlo + sw) = L;
        }
        #pragma unroll
        for (int i = 0; i < 4; i++) {
            const int f   = tid + i * 256;
            const int row = f >> 4;
            const int c   = f & 15;
            uint2 H, L;
            split4(vb[i], H, L);
            const uint32_t sw = sw128((uint32_t)(row * 128 + c * 8));
            *(uint2*)(sBhi + sw) = H;
            *(uint2*)(sBlo + sw) = L;
        }
        __syncthreads();

        #pragma unroll
        for (int ks = 0; ks < 4; ks++) {
            uint32_t ah[2][4], al[2][4];
            #pragma unroll
            for (int mf = 0; mf < 2; mf++) {
                const uint32_t row = (uint32_t)(mw*32 + mf*16 + aRowHalf*8 + rr);
                const uint32_t off = sw128(row * 128 + (uint32_t)(ks*16 + aKHalf*8) * 2);
                ldmx4(ah[mf], baseAhi + off);
                ldmx4(al[mf], baseAlo + off);
            }
            uint32_t bh[2][4], bl[2][4];
            #pragma unroll
            for (int pr = 0; pr < 2; pr++) {
                const uint32_t n   = (uint32_t)(nw*32 + pr*16 + bNb*8 + rr);
                const uint32_t off = sw128(n * 128 + (uint32_t)(ks*16 + bKHalf*8) * 2);
                ldmx4(bh[pr], baseBhi + off);
                ldmx4(bl[pr], baseBlo + off);
            }
            #pragma unroll
            for (int mf = 0; mf < 2; mf++) {
                #pragma unroll
                for (int nb = 0; nb < 4; nb++) {
                    const uint32_t B0h = bh[nb>>1][(nb&1)*2+0];
                    const uint32_t B1h = bh[nb>>1][(nb&1)*2+1];
                    const uint32_t B0l = bl[nb>>1][(nb&1)*2+0];
                    const uint32_t B1l = bl[nb>>1][(nb&1)*2+1];
                    mma_bf16(acc[mf][nb], ah[mf], B0h, B1h);
                    mma_bf16(acc[mf][nb], ah[mf], B0l, B1l);
                    mma_bf16(acc[mf][nb], al[mf], B0h, B1h);
                }
            }
        }
    }

    const int gID = lane >> 2;
    const int tg  = lane & 3;
    const float clipv = (QKV && which < 3) ? 10.f : 100.f;

    #pragma unroll
    for (int mf = 0; mf < 2; mf++) {
        #pragma unroll
        for (int nb = 0; nb < 4; nb++) {
            const int colL = nw*32 + nb*8 + tg*2;
            const float bb0 = bias[n0 + colL];
            const float bb1 = bias[n0 + colL + 1];
            #pragma unroll
            for (int half = 0; half < 2; half++) {
                const int m = m0 + mw*32 + mf*16 + half*8 + gID;
                float2 v;
                v.x = fminf(fmaxf(acc[mf][nb][half*2+0] + bb0, -clipv), clipv);
                v.y = fminf(fmaxf(acc[mf][nb][half*2+1] + bb1, -clipv), clipv);
                if (QKV && which < 3) {
                    const int b_ = m >> 11;
                    const int t  = m & (SEQ - 1);
                    const int h  = bx & 15;
                    float* dst = (which == 0) ? g_Q : (which == 1) ? g_K : g_V;
                    *(float2*)(dst + (((size_t)(b_*NHEAD + h))*SEQ + t)*DK + colL) = v;
                } else {
                    *(float2*)(outp + (size_t)m * D_MODEL + n0 + colL) = v;
                }
            }
        }
    }
}

// ---------------------------------------------------------------------------
// HMMA flash attention, v2.
//  - Q pre-scaled by 0.125 at load (lossless power of two).
//  - Max-free softmax: scores clipped to [-50,50] so p=exp(s) is always in
//    fp32 range (e^50=5e21, l<=2048*e^50=1e25; e^-50=2e-22). Reference's
//    rowmax subtraction cancels in p/sum(p); its exp-clamp and +1e-10 eps
//    differ by <=2e-6 relative. Masked keys: s=-10000 -> p=0 exactly.
//  - V stored row-major like K; PV B-fragments via ldmatrix.trans
//    (lane kk=lane&15 -> key row, dh=lane>>4 -> d half;
//     regs {r0,r1},{r2,r3} = b0/b1 of the two n8 d-groups).
// smem overlay: phase0 [0,16K)=Qhi [16K,32K)=Qlo;
//   per tile [0,8K)=Khi [8K,16K)=Klo [16K,24K)=Vhi [24K,32K)=Vlo.
// ---------------------------------------------------------------------------
__global__ __launch_bounds__(256, 1)
void attn_hmma_kernel(const unsigned char* __restrict__ mask)
{
    __shared__ __align__(1024) unsigned char sbuf[32768];
    __shared__ unsigned char smask[64];

    const int tid  = threadIdx.x;
    const int wid  = tid >> 5;
    const int lane = tid & 31;
    const int gID  = lane >> 2;
    const int tg   = lane & 3;

    const int blk      = lane >> 3;
    const int rr       = lane & 7;
    const int aRowHalf = blk & 1;
    const int aKHalf   = blk >> 1;
    const int bNb      = blk >> 1;
    const int bKHalf   = blk & 1;

    // trans-ldmatrix lane addressing for V (B operand of PV)
    const int vKey = lane & 15;       // key row within 16-key group
    const int vDh  = lane >> 4;       // d half (0: d0-7, 1: d8-15)

    const int qt = blockIdx.x;     // 0..15
    const int h  = blockIdx.y;     // 0..15
    const int b  = blockIdx.z;     // 0..3
    const int m0 = qt * 128;

    const size_t headoff = ((size_t)(b*NHEAD + h))*SEQ*DK;
    const float* Qb = g_Q + headoff;
    const float* Kb = g_K + headoff;
    const float* Vb = g_V + headoff;
    const unsigned char* mb = mask + (size_t)b*SEQ;

    const uint32_t sb = smem_u32(sbuf);

    // ---- Phase 0: Q tile 128x64 * 0.125 -> split bf16 -> smem -> registers
    #pragma unroll
    for (int i = 0; i < 8; i++) {
        const int f   = tid + i * 256;
        const int row = f >> 4;
        const int c   = f & 15;
        float4 v = *(const float4*)(Qb + (size_t)(m0 + row) * DK + c * 4);
        v.x *= 0.125f; v.y *= 0.125f; v.z *= 0.125f; v.w *= 0.125f;
        uint2 H, L;
        split4(v, H, L);
        const uint32_t sw = sw128((uint32_t)(row * 128 + c * 8));
        *(uint2*)(sbuf + sw)         = H;
        *(uint2*)(sbuf + 16384 + sw) = L;
    }
    __syncthreads();

    uint32_t qh[4][4], ql[4][4];
    #pragma unroll
    for (int ks = 0; ks < 4; ks++) {
        const uint32_t row = (uint32_t)(wid*16 + aRowHalf*8 + rr);
        const uint32_t off = sw128(row * 128 + (uint32_t)(ks*16 + aKHalf*8) * 2);
        ldmx4(qh[ks], sb + off);
        ldmx4(ql[ks], sb + 16384 + off);
    }
    __syncthreads();   // Q smem dead; overlay with K/V

    float oacc[8][4];
    #pragma unroll
    for (int nb = 0; nb < 8; nb++)
        #pragma unroll
        for (int i = 0; i < 4; i++) oacc[nb][i] = 0.f;
    float lrun0 = 0.f, lrun1 = 0.f;

    for (int kt = 0; kt < SEQ; kt += 64) {
        // ---- fill K and V (both row-major: row=key, 128B rows) + mask
        #pragma unroll
        for (int i = 0; i < 4; i++) {
            const int f   = tid + i * 256;
            const int row = f >> 4;
            const int c   = f & 15;
            float4 v = *(const float4*)(Kb + (size_t)(kt + row) * DK + c * 4);
            uint2 H, L;
            split4(v, H, L);
            const uint32_t sw = sw128((uint32_t)(row * 128 + c * 8));
            *(uint2*)(sbuf + sw)        = H;
            *(uint2*)(sbuf + 8192 + sw) = L;
        }
        #pragma unroll
        for (int i = 0; i < 4; i++) {
            const int f   = tid + i * 256;
            const int row = f >> 4;
            const int c   = f & 15;
            float4 v = *(const float4*)(Vb + (size_t)(kt + row) * DK + c * 4);
            uint2 H, L;
            split4(v, H, L);
            const uint32_t sw = sw128((uint32_t)(row * 128 + c * 8));
            *(uint2*)(sbuf + 16384 + sw) = H;
            *(uint2*)(sbuf + 24576 + sw) = L;
        }
        if (tid < 16) ((uint32_t*)smask)[tid] = *(const uint32_t*)(mb + kt + tid*4);
        __syncthreads();

        // ---- QK^T (Q pre-scaled): scores 16q x 64keys per warp
        float sacc[8][4];
        #pragma unroll
        for (int nt = 0; nt < 8; nt++)
            #pragma unroll
            for (int i = 0; i < 4; i++) sacc[nt][i] = 0.f;

        #pragma unroll
        for (int kg = 0; kg < 4; kg++) {
            #pragma unroll
            for (int ks = 0; ks < 4; ks++) {
                uint32_t bh[4], bl[4];
                const uint32_t row = (uint32_t)(kg*16 + bNb*8 + rr);
                const uint32_t off = sw128(row * 128 + (uint32_t)(ks*16 + bKHalf*8) * 2);
                ldmx4(bh, sb + off);
                ldmx4(bl, sb + 8192 + off);
                #pragma unroll
                for (int sub = 0; sub < 2; sub++) {
                    const int nt = kg*2 + sub;
                    mma_bf16(sacc[nt], qh[ks], bh[sub*2], bh[sub*2+1]);
                    mma_bf16(sacc[nt], qh[ks], bl[sub*2], bl[sub*2+1]);
                    mma_bf16(sacc[nt], ql[ks], bh[sub*2], bh[sub*2+1]);
                }
            }
        }

        // ---- clip, mask, p = exp(s); pack PV A-fragments; row sums
        uint32_t pah[4][4], pal[4][4];
        float rs0 = 0.f, rs1 = 0.f;
        #pragma unroll
        for (int nt = 0; nt < 8; nt++) {
            const int keyc = nt*8 + tg*2;
            const bool f0 = smask[keyc] != 0;
            const bool f1 = smask[keyc + 1] != 0;
            float s0 = fminf(fmaxf(sacc[nt][0], -50.f), 50.f); if (f0) s0 = -10000.f;
            float s1 = fminf(fmaxf(sacc[nt][1], -50.f), 50.f); if (f1) s1 = -10000.f;
            float s2 = fminf(fmaxf(sacc[nt][2], -50.f), 50.f); if (f0) s2 = -10000.f;
            float s3 = fminf(fmaxf(sacc[nt][3], -50.f), 50.f); if (f1) s3 = -10000.f;
            const float p0 = __expf(s0);
            const float p1 = __expf(s1);
            const float p2 = __expf(s2);
            const float p3 = __expf(s3);
            rs0 += p0 + p1;
            rs1 += p2 + p3;
            const int ks  = nt >> 1;
            const int sub = nt & 1;
            split_pack2(p0, p1, pah[ks][sub*2+0], pal[ks][sub*2+0]);
            split_pack2(p2, p3, pah[ks][sub*2+1], pal[ks][sub*2+1]);
        }
        rs0 += __shfl_xor_sync(0xffffffffu, rs0, 1);
        rs0 += __shfl_xor_sync(0xffffffffu, rs0, 2);
        rs1 += __shfl_xor_sync(0xffffffffu, rs1, 1);
        rs1 += __shfl_xor_sync(0xffffffffu, rs1, 2);
        lrun0 += rs0;
        lrun1 += rs1;

        // ---- PV: out += P(16x64) * V(64 x 64d); B via trans-ldmatrix
        #pragma unroll
        for (int dg = 0; dg < 4; dg++) {
            #pragma unroll
            for (int ks = 0; ks < 4; ks++) {
                uint32_t vh[4], vl[4];
                const uint32_t key = (uint32_t)(ks*16 + vKey);
                const uint32_t off = sw128(key * 128 + (uint32_t)(dg*16 + vDh*8) * 2);
                ldmx4t(vh, sb + 16384 + off);
                ldmx4t(vl, sb + 24576 + off);
                #pragma unroll
                for (int sub = 0; sub < 2; sub++) {
                    const int nb = dg*2 + sub;
                    mma_bf16(oacc[nb], pah[ks], vh[sub*2], vh[sub*2+1]);
                    mma_bf16(oacc[nb], pah[ks], vl[sub*2], vl[sub*2+1]);
                    mma_bf16(oacc[nb], pal[ks], vh[sub*2], vh[sub*2+1]);
                }
            }
        }
        __syncthreads();
    }

    // ---- normalize + store (ref's +1e-10 eps is <=1e-10 relative; omitted)
    const float inv0 = 1.f / lrun0;
    const float inv1 = 1.f / lrun1;
    const int row0 = m0 + wid*16 + gID;
    const int row1 = row0 + 8;
    float* c0 = g_ctx + ((size_t)(b*SEQ + row0))*D_MODEL + h*DK;
    float* c1 = g_ctx + ((size_t)(b*SEQ + row1))*D_MODEL + h*DK;
    #pragma unroll
    for (int nb = 0; nb < 8; nb++) {
        const int col = nb*8 + tg*2;
        float2 v0, v1;
        v0.x = oacc[nb][0]*inv0; v0.y = oacc[nb][1]*inv0;
        v1.x = oacc[nb][2]*inv1; v1.y = oacc[nb][3]*inv1;
        *(float2*)(c0 + col) = v0;
        *(float2*)(c1 + col) = v1;
    }
}

// ---------------------------------------------------------------------------
extern "C" void kernel_launch(void* const* d_in, const int* in_sizes, int n_in,
                              void* d_out, int out_size)
{
    const float* x  = (const float*)d_in[0];
    const unsigned char* mask = (const unsigned char*)d_in[1];
    const float* Wq = (const float*)d_in[2];
    const float* bq = (const float*)d_in[3];
    const float* Wk = (const float*)d_in[4];
    const float* bk = (const float*)d_in[5];
    const float* Wv = (const float*)d_in[6];
    const float* bv = (const float*)d_in[7];
    const float* Wo = (const float*)d_in[8];
    const float* bo = (const float*)d_in[9];
    float* out = (float*)d_out;

    hmma_gemm_kernel<true><<<dim3(48, M_ROWS/128), 256>>>(
        x, Wq, Wk, Wv, bq, bk, bv, nullptr);

    attn_hmma_kernel<<<dim3(SEQ/128, NHEAD, BATCH), 256>>>(mask);

    hmma_gemm_kernel<false><<<dim3(16, M_ROWS/128), 256>>>(
        nullptr, Wo, Wo, Wo, bo, bo, bo, out);
}